// round 10
// baseline (speedup 1.0000x reference)
#include <cuda_runtime.h>
#include <math.h>

#define IMG_H 480
#define IMG_W 640
#define NB    4
#define PS    (IMG_H * IMG_W)

#define BTX   32
#define BTY   4
#define TPW   64                   // 32 threads x 2 px wide
#define TPH   8                    // 4 threads x 2 px tall (spacing 4)
#define HALO  6
#define TILE_W 76                  // 64 + 12
#define TILE_H (TPH + 2 * HALO)    // 20

// float bit patterns of -2.0f / 0.0f / +2.0f live entirely in bits [31:30]
#define FB(o)  ((o) == -2 ? 0xC0000000u : ((o) == 2 ? 0x40000000u : 0u))
// pack (off_h, off_w) for candidate k: oh bits [31:30], ow bits [29:28]
#define PKC(k) (FB(2*((k)/3 - 1)) | (FB(2*((k)%3 - 1)) >> 2))

__device__ __forceinline__ constexpr unsigned maskRC(int R, int C) {
    // col taps (j=1,7): k in {1,4,7}; row taps (j=3,5): k in {3,4,5}; else all 9
    return ((R != 1) && (C == 1)) ? 0x92u :
           ((R == 1) && (C != 1)) ? 0x38u : 0x1FFu;
}
__device__ __forceinline__ constexpr int firstK(unsigned m) {
    return (m & 1u) ? 0 : ((m & 2u) ? 1 : 3);
}

// load one grid row (14 consecutive floats) as 7 LDS.64
#define LOADROW(dst, m) { \
    const float2* _s = (const float2*)&tile[ty + 2*(m)][2*tx]; \
    _Pragma("unroll") \
    for (int _q = 0; _q < 7; _q++) { \
        float2 _v = _s[_q]; dst[2*_q] = _v.x; dst[2*_q + 1] = _v.y; } }

// one tap-row group (3 taps x 2 pixels) using window rows Ra,Rb,Rc (r=0,1,2)
template<bool SAFE, int Rg>
__device__ __forceinline__ void doGroup(
    const float (&Ra)[14], const float (&Rb)[14], const float (&Rc)[14],
    float cen0, float cen1, int x0, int y, float* __restrict__ op)
{
    bool yok = true;
    if (!SAFE) yok = (unsigned)(y + 4 * (Rg - 1)) < (unsigned)IMG_H;

#pragma unroll
    for (int C = 0; C < 3; C++) {
        const int j = 3 * Rg + C;
        const unsigned mask = maskRC(Rg, C);
        const int fk = firstK(mask);

        unsigned pk0, pk1;
#pragma unroll
        for (int p = 0; p < 2; p++) {
            const float cen = (p == 0) ? cen0 : cen1;
            float best = 0.0f;
            unsigned pk = 0u;
            bool first = true;
#pragma unroll
            for (int k = 0; k < 9; k++) {
                if (!((mask >> k) & 1u)) continue;
                const int r = k / 3;
                const int c = k % 3;
                const int idx = p + 4 * C + 2 * c;
                float v = ((r == 0) ? Ra[idx] : (r == 1) ? Rb[idx] : Rc[idx]) - cen;
                if (first) { best = v; pk = PKC(k); first = false; }
                else {
                    bool pr = fabsf(v) < fabsf(best);  // strict <: first wins
                    best = pr ? v : best;
                    pk   = pr ? PKC(k) : pk;
                }
            }
            if (!SAFE) {
                // intermediate index OOB -> all allowed samples tie -> first k
                bool xok = (unsigned)(x0 + p + 4 * (C - 1)) < (unsigned)IMG_W;
                if (!(yok && xok)) pk = PKC(fk);
            }
            if (p == 0) pk0 = pk; else pk1 = pk;
        }

        float2 hv = make_float2(__uint_as_float(pk0 & 0xC0000000u),
                                __uint_as_float(pk1 & 0xC0000000u));
        float2 wv = make_float2(__uint_as_float((pk0 << 2) & 0xC0000000u),
                                __uint_as_float((pk1 << 2) & 0xC0000000u));
        *(float2*)(op + (size_t)j * PS)       = hv;
        *(float2*)(op + (size_t)(j + 9) * PS) = wv;
    }
}

template<bool SAFE>
__device__ __forceinline__ void computeT(
    const float (&tile)[TILE_H][TILE_W],
    int tx, int ty, int x0, int yA, float* __restrict__ opA)
{
    float* __restrict__ opB = opA + 4 * IMG_W;
    const int yB = yA + 4;

    float cA0, cA1, cB0, cB1;
    { float2 c = *(const float2*)&tile[ty + 6][2 * tx + 6];  cA0 = c.x; cA1 = c.y; }
    { float2 c = *(const float2*)&tile[ty + 10][2 * tx + 6]; cB0 = c.x; cB1 = c.y; }

    // sliding 3-row window over grid rows m = 0..8 (tile rows ty + 2m)
    // pxA group R uses m = {2R, 2R+1, 2R+2}; pxB (y+4) group R uses m+2
    float R0[14], R1[14], R2[14];
    LOADROW(R0, 0) LOADROW(R1, 1) LOADROW(R2, 2)
    doGroup<SAFE, 0>(R0, R1, R2, cA0, cA1, x0, yA, opA);
    LOADROW(R0, 3) LOADROW(R1, 4)
    doGroup<SAFE, 1>(R2, R0, R1, cA0, cA1, x0, yA, opA);   // m {2,3,4}
    doGroup<SAFE, 0>(R2, R0, R1, cB0, cB1, x0, yB, opB);   // m {2,3,4}
    LOADROW(R2, 5) LOADROW(R0, 6)
    doGroup<SAFE, 2>(R1, R2, R0, cA0, cA1, x0, yA, opA);   // m {4,5,6}
    doGroup<SAFE, 1>(R1, R2, R0, cB0, cB1, x0, yB, opB);   // m {4,5,6}
    LOADROW(R1, 7) LOADROW(R2, 8)
    doGroup<SAFE, 2>(R0, R1, R2, cB0, cB1, x0, yB, opB);   // m {6,7,8}
}

__global__ void __launch_bounds__(BTX * BTY, 8)
DepthOffset_kernel(const float* __restrict__ depth, float* __restrict__ out)
{
    __shared__ __align__(16) float tile[TILE_H][TILE_W];

    const int b   = blockIdx.z;
    const int bx0 = blockIdx.x * TPW;
    const int by0 = blockIdx.y * TPH;
    const int tx  = threadIdx.x, ty = threadIdx.y;
    const int t   = ty * BTX + tx;

    const float* __restrict__ dp = depth + b * PS;

    // whole tile footprint (incl. halo) inside the image?
    const bool safe = (bx0 >= HALO) && (bx0 + TPW + HALO <= IMG_W) &&
                      (by0 >= HALO) && (by0 + TPH + HALO <= IMG_H);

    if (safe) {
        for (int i = t; i < TILE_H * TILE_W; i += BTX * BTY) {
            int r = i / TILE_W;
            int c = i - r * TILE_W;
            tile[r][c] = dp[(by0 - HALO + r) * IMG_W + (bx0 - HALO + c)];
        }
    } else {
        for (int i = t; i < TILE_H * TILE_W; i += BTX * BTY) {
            int r  = i / TILE_W;
            int c  = i - r * TILE_W;
            int gy = by0 - HALO + r;
            int gx = bx0 - HALO + c;
            float v = 0.0f;
            if ((unsigned)gy < (unsigned)IMG_H && (unsigned)gx < (unsigned)IMG_W)
                v = dp[gy * IMG_W + gx];
            tile[r][c] = v;
        }
    }
    __syncthreads();

    const int x0 = bx0 + 2 * tx;
    const int yA = by0 + ty;
    float* __restrict__ opA = out + (size_t)(b * 18) * PS + yA * IMG_W + x0;

    if (safe)
        computeT<true >(tile, tx, ty, x0, yA, opA);
    else
        computeT<false>(tile, tx, ty, x0, yA, opA);
}

extern "C" void kernel_launch(void* const* d_in, const int* in_sizes, int n_in,
                              void* d_out, int out_size)
{
    const float* depth = (const float*)d_in[0];
    float* out = (float*)d_out;

    dim3 block(BTX, BTY);
    dim3 grid(IMG_W / TPW, IMG_H / TPH, NB);   // 10 x 60 x 4
    DepthOffset_kernel<<<grid, block>>>(depth, out);
}